// round 1
// baseline (speedup 1.0000x reference)
#include <cuda_runtime.h>
#include <math.h>
#include <float.h>

#define NT 1024
#define NMAX 8192
#define CH (NMAX / NT)   // 8 elements per thread

static __device__ __forceinline__ void lse_comb(float& m, float& s, float m2, float s2) {
    float M = fmaxf(m, m2);
    s = s * __expf(m - M) + s2 * __expf(m2 - M);
    m = M;
}

extern "C" __global__ void __launch_bounds__(NT, 1)
surv_loss_kernel(const float* __restrict__ outputs,
                 const int* __restrict__ y,
                 const float* __restrict__ t,
                 const int* __restrict__ c,
                 float* __restrict__ out,
                 int B, int K)
{
    extern __shared__ char smem_raw[];
    float*    t_s    = (float*)smem_raw;                 // [NMAX]
    unsigned* v_s    = (unsigned*)(t_s + NMAX);          // [NMAX] idx | (c<<31)
    float*    risk_o = (float*)(v_s + NMAX);             // [NMAX] original order
    float*    mexc   = risk_o + NMAX;                    // [NMAX]
    float*    sexc   = mexc + NMAX;                      // [NMAX]
    int*      grp    = (int*)(sexc + NMAX);              // [NMAX]
    float*    m_blk  = (float*)(grp + NMAX);             // [NT]
    float*    s_blk  = m_blk + NT;                       // [NT]
    int*      iblk   = (int*)(s_blk + NT);               // [NT]

    const int tid = threadIdx.x;
    const float EPSC = 1e-7f;
    const float MNEG = -3.0e38f;

    // ---------- Phase A: per-row hazards -> risk, NLL (coalesced) ----------
    float nll_acc = 0.f;
    for (int u = 0; u < CH; u++) {
        int r = tid + u * NT;
        if (r < B) {
            float hz[8], Sc[8];
            float Sp = 1.f, Ssum = 0.f;
            if (K == 4) {
                float4 o4 = ((const float4*)outputs)[r];
                float o[4] = {o4.x, o4.y, o4.z, o4.w};
                #pragma unroll
                for (int k = 0; k < 4; k++) {
                    float h = 1.f / (1.f + __expf(-o[k]));
                    hz[k] = h;
                    Sp *= (1.f - h);
                    Sc[k] = Sp;
                    Ssum += Sp;
                }
            } else {
                for (int k = 0; k < K && k < 8; k++) {
                    float h = 1.f / (1.f + __expf(-outputs[(size_t)r * K + k]));
                    hz[k] = h;
                    Sp *= (1.f - h);
                    Sc[k] = Sp;
                    Ssum += Sp;
                }
            }
            float risk = -Ssum;
            int yi = y[r];
            float s_prev = fmaxf((yi == 0) ? 1.f : Sc[yi - 1], EPSC);
            float h_this = fmaxf(hz[yi], EPSC);
            float s_this = fmaxf(Sc[yi], EPSC);
            float cf = (float)c[r];
            nll_acc += -(1.f - cf) * (__logf(s_prev) + __logf(h_this))
                       - cf * __logf(s_this);
            t_s[r]    = t[r];
            v_s[r]    = (unsigned)r | (c[r] ? 0x80000000u : 0u);
            risk_o[r] = risk;
        } else {
            t_s[r]    = -FLT_MAX;       // pads sort to the end, marked invalid
            v_s[r]    = 0x80000000u;
            risk_o[r] = 0.f;
        }
    }
    __syncthreads();

    // ---------- Phase B: bitonic sort by t descending (carry v) ----------
    for (int k = 2; k <= NMAX; k <<= 1) {
        for (int j = k >> 1; j > 0; j >>= 1) {
            for (int i = tid; i < NMAX; i += NT) {
                int l = i ^ j;
                if (l > i) {
                    float ti = t_s[i], tl = t_s[l];
                    bool desc = ((i & k) == 0);
                    bool sw = desc ? (ti < tl) : (ti > tl);
                    if (sw) {
                        t_s[i] = tl; t_s[l] = ti;
                        unsigned v = v_s[i]; v_s[i] = v_s[l]; v_s[l] = v;
                    }
                }
            }
            __syncthreads();
        }
    }

    // ---------- Phase C: tie-group start index via inclusive max-scan ----------
    const int base = tid * CH;
    {
        int run = 0;
        #pragma unroll
        for (int u = 0; u < CH; u++) {
            int p = base + u;
            int b = (p == 0 || t_s[p] != t_s[p - 1]) ? p : 0;
            run = max(run, b);
            grp[p] = run;
        }
        iblk[tid] = run;
        __syncthreads();
        for (int off = 1; off < NT; off <<= 1) {
            int v = (tid >= off) ? iblk[tid - off] : 0;
            __syncthreads();
            if (tid >= off) iblk[tid] = max(iblk[tid], v);
            __syncthreads();
        }
        int ex = (tid == 0) ? 0 : iblk[tid - 1];
        #pragma unroll
        for (int u = 0; u < CH; u++) {
            int p = base + u;
            grp[p] = max(grp[p], ex);
        }
    }
    __syncthreads();

    // ---------- Phase D: exclusive logsumexp scan over sorted risks ----------
    float rloc[CH];
    {
        float m = MNEG, s = 0.f;
        #pragma unroll
        for (int u = 0; u < CH; u++) {
            int p = base + u;
            float r = risk_o[v_s[p] & 0x7FFFFFFFu];
            rloc[u] = r;
            mexc[p] = m; sexc[p] = s;
            lse_comb(m, s, r, 1.f);
        }
        m_blk[tid] = m; s_blk[tid] = s;
        __syncthreads();
        for (int off = 1; off < NT; off <<= 1) {
            float m2 = MNEG, s2 = 0.f;
            if (tid >= off) { m2 = m_blk[tid - off]; s2 = s_blk[tid - off]; }
            __syncthreads();
            if (tid >= off) {
                float M = m_blk[tid], S = s_blk[tid];
                lse_comb(M, S, m2, s2);
                m_blk[tid] = M; s_blk[tid] = S;
            }
            __syncthreads();
        }
        float mex = MNEG, sex = 0.f;
        if (tid > 0) { mex = m_blk[tid - 1]; sex = s_blk[tid - 1]; }
        #pragma unroll
        for (int u = 0; u < CH; u++) {
            int p = base + u;
            float M = mexc[p], S = sexc[p];
            lse_comb(M, S, mex, sex);
            mexc[p] = M; sexc[p] = S;
        }
    }
    __syncthreads();

    // ---------- Phase E: per-element rank contributions ----------
    float per_acc = 0.f;
    int cnt_acc = 0;
    #pragma unroll
    for (int u = 0; u < CH; u++) {
        int p = base + u;
        unsigned v = v_s[p];
        int q = grp[p];                       // strictly-greater prefix = [0, q)
        if (!(v & 0x80000000u) && q > 0) {
            float lse = mexc[q] + __logf(sexc[q]);
            per_acc += lse - rloc[u];
            cnt_acc++;
        }
    }

    // ---------- Final reduction + combine ----------
    __syncthreads();
    m_blk[tid] = per_acc;
    s_blk[tid] = nll_acc;
    iblk[tid]  = cnt_acc;
    __syncthreads();
    for (int off = NT >> 1; off > 0; off >>= 1) {
        if (tid < off) {
            m_blk[tid] += m_blk[tid + off];
            s_blk[tid] += s_blk[tid + off];
            iblk[tid]  += iblk[tid + off];
        }
        __syncthreads();
    }
    if (tid == 0) {
        float rank = (iblk[0] > 0) ? (m_blk[0] / (float)iblk[0]) : 0.f;
        out[0] = s_blk[0] / (float)B + 0.5f * rank;
    }
}

extern "C" void kernel_launch(void* const* d_in, const int* in_sizes, int n_in,
                              void* d_out, int out_size)
{
    const float* outputs = (const float*)d_in[0];
    const int*   y       = (const int*)d_in[1];
    const float* t       = (const float*)d_in[2];
    const int*   c       = (const int*)d_in[3];
    float*       out     = (float*)d_out;

    int B = in_sizes[2];
    int K = (B > 0) ? in_sizes[0] / B : 0;

    size_t smem = (size_t)NMAX * 4 * 6 + (size_t)NT * 4 * 3;  // 208896 bytes
    cudaFuncSetAttribute(surv_loss_kernel,
                         cudaFuncAttributeMaxDynamicSharedMemorySize, (int)smem);
    surv_loss_kernel<<<1, NT, smem>>>(outputs, y, t, c, out, B, K);
}

// round 2
// speedup vs baseline: 5.2895x; 5.2895x over previous
#include <cuda_runtime.h>
#include <math.h>
#include <float.h>

#define BN      8192
#define KA_BLK  256
#define KA_GRID (BN / KA_BLK)        // 32
#define CHUNK   512
#define NCHUNK  (BN / CHUNK)         // 16
#define RTILE   1024
#define NTILE   (BN / RTILE)         // 8
#define KB_BLK  256
#define RPT     4                    // rows per thread in kernel B

__device__ float  g_risk[BN];
__device__ float2 g_te[BN];                  // (t[j], exp(risk[j]))
__device__ float  g_part[NCHUNK][BN];
__device__ float  g_nll[KA_GRID];

// ---------------- Kernel A: per-row risk, e=exp(risk), NLL ----------------
extern "C" __global__ void __launch_bounds__(KA_BLK)
surv_rows_kernel(const float* __restrict__ outputs,
                 const int* __restrict__ y,
                 const float* __restrict__ t,
                 const int* __restrict__ c)
{
    __shared__ float red[KA_BLK];
    const int tid = threadIdx.x;
    const int r = blockIdx.x * KA_BLK + tid;
    const float EPSC = 1e-7f;

    float4 o4 = ((const float4*)outputs)[r];
    float o[4] = {o4.x, o4.y, o4.z, o4.w};
    float hz[4], Sc[4];
    float Sp = 1.f, Ssum = 0.f;
    #pragma unroll
    for (int k = 0; k < 4; k++) {
        float h = 1.f / (1.f + __expf(-o[k]));
        hz[k] = h;
        Sp *= (1.f - h);
        Sc[k] = Sp;
        Ssum += Sp;
    }
    float risk = -Ssum;

    int yi = y[r];
    float s_prev = fmaxf((yi == 0) ? 1.f : Sc[yi - 1], EPSC);
    float h_this = fmaxf(hz[yi], EPSC);
    float s_this = fmaxf(Sc[yi], EPSC);
    float cf = (float)c[r];
    float nll = -(1.f - cf) * (__logf(s_prev) + __logf(h_this))
                - cf * __logf(s_this);

    g_risk[r] = risk;
    g_te[r]   = make_float2(t[r], __expf(risk));

    // fixed-order block reduction of nll
    red[tid] = nll;
    __syncthreads();
    for (int off = KA_BLK >> 1; off > 0; off >>= 1) {
        if (tid < off) red[tid] += red[tid + off];
        __syncthreads();
    }
    if (tid == 0) g_nll[blockIdx.x] = red[0];
}

// ---------------- Kernel B: masked pair sums ----------------
// block (tile, chunk): rows r = tile*RTILE + tid + k*KB_BLK (k<RPT),
// j in [chunk*CHUNK, chunk*CHUNK+CHUNK)
extern "C" __global__ void __launch_bounds__(KB_BLK)
surv_pairs_kernel()
{
    __shared__ float2 te[CHUNK];
    const int tid   = threadIdx.x;
    const int tile  = blockIdx.x;
    const int chunk = blockIdx.y;

    #pragma unroll
    for (int i = tid; i < CHUNK; i += KB_BLK)
        te[i] = g_te[chunk * CHUNK + i];

    float ti[RPT], sum[RPT];
    #pragma unroll
    for (int k = 0; k < RPT; k++) {
        ti[k]  = g_te[tile * RTILE + tid + k * KB_BLK].x;
        sum[k] = 0.f;
    }
    __syncthreads();

    #pragma unroll 8
    for (int j = 0; j < CHUNK; j++) {
        float2 v = te[j];
        #pragma unroll
        for (int k = 0; k < RPT; k++)
            sum[k] += (v.x > ti[k]) ? v.y : 0.f;
    }

    #pragma unroll
    for (int k = 0; k < RPT; k++)
        g_part[chunk][tile * RTILE + tid + k * KB_BLK] = sum[k];
}

// ---------------- Kernel C: finalize ----------------
extern "C" __global__ void __launch_bounds__(1024)
surv_final_kernel(const int* __restrict__ c, float* __restrict__ out)
{
    __shared__ float per_s[1024];
    __shared__ float nll_s[1024];
    __shared__ int   cnt_s[1024];
    const int tid = threadIdx.x;

    float per = 0.f;
    int   cnt = 0;
    #pragma unroll
    for (int u = 0; u < BN / 1024; u++) {
        int r = tid + u * 1024;
        float sum = 0.f;
        #pragma unroll
        for (int ch = 0; ch < NCHUNK; ch++)
            sum += g_part[ch][r];
        bool valid = (c[r] == 0) && (sum > 0.f);
        if (valid) {
            per += __logf(sum) - g_risk[r];
            cnt += 1;
        }
    }

    per_s[tid] = per;
    cnt_s[tid] = cnt;
    nll_s[tid] = (tid < KA_GRID) ? g_nll[tid] : 0.f;
    __syncthreads();
    for (int off = 512; off > 0; off >>= 1) {
        if (tid < off) {
            per_s[tid] += per_s[tid + off];
            cnt_s[tid] += cnt_s[tid + off];
            nll_s[tid] += nll_s[tid + off];
        }
        __syncthreads();
    }
    if (tid == 0) {
        float rank = (cnt_s[0] > 0) ? (per_s[0] / (float)cnt_s[0]) : 0.f;
        out[0] = nll_s[0] / (float)BN + 0.5f * rank;
    }
}

extern "C" void kernel_launch(void* const* d_in, const int* in_sizes, int n_in,
                              void* d_out, int out_size)
{
    const float* outputs = (const float*)d_in[0];
    const int*   y       = (const int*)d_in[1];
    const float* t       = (const float*)d_in[2];
    const int*   c       = (const int*)d_in[3];
    float*       out     = (float*)d_out;

    surv_rows_kernel<<<KA_GRID, KA_BLK>>>(outputs, y, t, c);
    surv_pairs_kernel<<<dim3(NTILE, NCHUNK), KB_BLK>>>();
    surv_final_kernel<<<1, 1024>>>(c, out);
}

// round 3
// speedup vs baseline: 5.8111x; 1.0986x over previous
#include <cuda_runtime.h>
#include <math.h>
#include <float.h>

#define NB    8192
#define CHK   512
#define NCH   16            // NB / CHK, = grid of kernel 1
#define T1    256
#define QB    32            // kernel-2 blocks
#define QT    256           // kernel-2 threads (QB*QT == NB)

__device__ __align__(16) float g_risk[NB];
__device__ __align__(16) float g_tsrt[NB];
__device__ __align__(16) float g_pe[NB];
__device__ float g_nll[NCH];
__device__ float g_per[QB];
__device__ int   g_cnt[QB];
__device__ int   g_ticket;

// ---------- Kernel 1: rows + per-chunk sort + prefix sums ----------
extern "C" __global__ void __launch_bounds__(T1)
surv_prep_kernel(const float* __restrict__ outputs,
                 const int* __restrict__ y,
                 const float* __restrict__ t,
                 const int* __restrict__ c)
{
    __shared__ float ts[CHK];
    __shared__ float es[CHK];
    __shared__ float red[T1];
    const int tid = threadIdx.x;
    const int blk = blockIdx.x;
    const float EPSC = 1e-7f;

    float nll_acc = 0.f;
    #pragma unroll
    for (int u = 0; u < CHK / T1; u++) {
        int li = tid + u * T1;
        int r  = blk * CHK + li;
        float4 o4 = ((const float4*)outputs)[r];
        float o[4] = {o4.x, o4.y, o4.z, o4.w};
        float hz[4], Sc[4];
        float Sp = 1.f, Ssum = 0.f;
        #pragma unroll
        for (int k = 0; k < 4; k++) {
            float h = 1.f / (1.f + __expf(-o[k]));
            hz[k] = h;
            Sp *= (1.f - h);
            Sc[k] = Sp;
            Ssum += Sp;
        }
        float risk = -Ssum;
        int yi = y[r];
        float s_prev = fmaxf((yi == 0) ? 1.f : Sc[yi - 1], EPSC);
        float h_this = fmaxf(hz[yi], EPSC);
        float s_this = fmaxf(Sc[yi], EPSC);
        float cf = (float)c[r];
        nll_acc += -(1.f - cf) * (__logf(s_prev) + __logf(h_this))
                   - cf * __logf(s_this);

        g_risk[r] = risk;
        ts[li] = t[r];
        es[li] = __expf(risk);
    }

    // NLL partial (fixed order)
    red[tid] = nll_acc;
    __syncthreads();
    for (int off = T1 >> 1; off > 0; off >>= 1) {
        if (tid < off) red[tid] += red[tid + off];
        __syncthreads();
    }
    if (tid == 0) g_nll[blk] = red[0];

    // bitonic sort (t desc, carry e)
    for (int k = 2; k <= CHK; k <<= 1) {
        for (int j = k >> 1; j > 0; j >>= 1) {
            #pragma unroll
            for (int u = 0; u < CHK / T1; u++) {
                int i = tid + u * T1;
                int l = i ^ j;
                if (l > i) {
                    float a = ts[i], b = ts[l];
                    bool desc = ((i & k) == 0);
                    bool sw = desc ? (a < b) : (a > b);
                    if (sw) {
                        ts[i] = b; ts[l] = a;
                        float e = es[i]; es[i] = es[l]; es[l] = e;
                    }
                }
            }
            __syncthreads();
        }
    }

    // inclusive prefix sum of es (Hillis-Steele, 2 elems/thread)
    for (int off = 1; off < CHK; off <<= 1) {
        float a0 = (tid >= off) ? es[tid - off] : 0.f;
        float a1 = es[tid + T1 - off];        // tid+256-off >= 0 for off<=256
        __syncthreads();
        es[tid]      += a0;
        es[tid + T1] += a1;
        __syncthreads();
    }

    #pragma unroll
    for (int u = 0; u < CHK / T1; u++) {
        int li = tid + u * T1;
        g_tsrt[blk * CHK + li] = ts[li];
        g_pe[blk * CHK + li]   = es[li];
    }
}

// ---------- Kernel 2: rank queries + finalize (last block) ----------
extern "C" __global__ void __launch_bounds__(QT)
surv_query_kernel(const float* __restrict__ t,
                  const int* __restrict__ c,
                  float* __restrict__ out)
{
    extern __shared__ float sm[];
    float* t_s  = sm;            // [NB]
    float* pe_s = sm + NB;       // [NB]
    __shared__ float redf[QT];
    __shared__ int   redi[QT];
    __shared__ int   is_last;

    const int tid = threadIdx.x;
    const int blk = blockIdx.x;

    // load sorted tables (coalesced float4)
    #pragma unroll
    for (int i = tid; i < NB / 4; i += QT) {
        ((float4*)t_s)[i]  = ((const float4*)g_tsrt)[i];
        ((float4*)pe_s)[i] = ((const float4*)g_pe)[i];
    }

    const int r = blk * QT + tid;
    const float ti = t[r];
    __syncthreads();

    // 16 interleaved binary searches: rank_w = #{j in chunk w : t_j > ti}
    int cw[NCH];
    #pragma unroll
    for (int w = 0; w < NCH; w++) cw[w] = 0;

    #pragma unroll
    for (int s = CHK / 2; s > 0; s >>= 1) {
        #pragma unroll
        for (int w = 0; w < NCH; w++)
            cw[w] += (t_s[w * CHK + cw[w] + s - 1] > ti) ? s : 0;
    }
    #pragma unroll
    for (int w = 0; w < NCH; w++)
        cw[w] += (t_s[w * CHK + cw[w]] > ti) ? 1 : 0;

    float sum = 0.f;
    int cnt = 0;
    #pragma unroll
    for (int w = 0; w < NCH; w++) {
        if (cw[w] > 0) {
            sum += pe_s[w * CHK + cw[w] - 1];
            cnt += cw[w];
        }
    }

    bool valid = (c[r] == 0) && (cnt > 0);
    float per = valid ? (__logf(sum) - g_risk[r]) : 0.f;
    int   cv  = valid ? 1 : 0;

    // block reduction (fixed order)
    redf[tid] = per;
    redi[tid] = cv;
    __syncthreads();
    for (int off = QT >> 1; off > 0; off >>= 1) {
        if (tid < off) {
            redf[tid] += redf[tid + off];
            redi[tid] += redi[tid + off];
        }
        __syncthreads();
    }
    if (tid == 0) {
        g_per[blk] = redf[0];
        g_cnt[blk] = redi[0];
        __threadfence();
        int tk = atomicAdd(&g_ticket, 1);
        is_last = (tk == QB - 1) ? 1 : 0;
    }
    __syncthreads();

    if (is_last && tid == 0) {
        float per_t = 0.f, nll_t = 0.f;
        int cnt_t = 0;
        #pragma unroll
        for (int b = 0; b < QB; b++) { per_t += g_per[b]; cnt_t += g_cnt[b]; }
        #pragma unroll
        for (int b = 0; b < NCH; b++) nll_t += g_nll[b];
        float rank = (cnt_t > 0) ? (per_t / (float)cnt_t) : 0.f;
        out[0] = nll_t / (float)NB + 0.5f * rank;
        g_ticket = 0;   // self-reset for graph replay
    }
}

extern "C" void kernel_launch(void* const* d_in, const int* in_sizes, int n_in,
                              void* d_out, int out_size)
{
    const float* outputs = (const float*)d_in[0];
    const int*   y       = (const int*)d_in[1];
    const float* t       = (const float*)d_in[2];
    const int*   c       = (const int*)d_in[3];
    float*       out     = (float*)d_out;

    size_t smem2 = (size_t)NB * 2 * sizeof(float);   // 64 KB
    cudaFuncSetAttribute(surv_query_kernel,
                         cudaFuncAttributeMaxDynamicSharedMemorySize, (int)smem2);

    surv_prep_kernel<<<NCH, T1>>>(outputs, y, t, c);
    surv_query_kernel<<<QB, QT, smem2>>>(t, c, out);
}